// round 12
// baseline (speedup 1.0000x reference)
#include <cuda_runtime.h>
#include <cuda_fp16.h>
#include <cstdint>

// Problem constants
#define B_   8
#define C_   256
#define H_   64
#define W_   64
#define OC_  256
#define K_   9
#define HW_  4096
#define CK_  2304

// ---------------------------------------------------------------------------
// Device scratch (allocation-free rule)
// ---------------------------------------------------------------------------
__device__ __align__(256) __half g_cols[(size_t)B_ * CK_ * HW_];  // 151 MB, [b][k*256+c][pix]
__device__ __align__(256) __half g_w[OC_ * CK_];                  // [oc][k*256+c]
__device__ __align__(256) __half g_xth[(size_t)B_ * HW_ * C_];    // 67 MB, [b][pix][c] fp16

// ---------------------------------------------------------------------------
// Helpers
// ---------------------------------------------------------------------------
__device__ __forceinline__ uint32_t smem_u32(const void* p) {
    uint32_t a;
    asm("{ .reg .u64 t; cvta.to.shared.u64 t, %1; cvt.u32.u64 %0, t; }"
        : "=r"(a) : "l"(p));
    return a;
}

__device__ __forceinline__ void cpasync16(uint32_t s, const void* g) {
    asm volatile("cp.async.cg.shared.global [%0], [%1], 16;" :: "r"(s), "l"(g));
}

__device__ __forceinline__ void ldsm_x4(uint32_t* r, uint32_t addr) {
    asm volatile("ldmatrix.sync.aligned.m8n8.x4.shared.b16 {%0,%1,%2,%3}, [%4];"
                 : "=r"(r[0]), "=r"(r[1]), "=r"(r[2]), "=r"(r[3]) : "r"(addr));
}

__device__ __forceinline__ void ldsm_x4_t(uint32_t* r, uint32_t addr) {
    asm volatile("ldmatrix.sync.aligned.m8n8.x4.trans.shared.b16 {%0,%1,%2,%3}, [%4];"
                 : "=r"(r[0]), "=r"(r[1]), "=r"(r[2]), "=r"(r[3]) : "r"(addr));
}

__device__ __forceinline__ void mma_f16(float* d, const uint32_t* a,
                                        uint32_t b0, uint32_t b1) {
    asm volatile(
        "mma.sync.aligned.m16n8k16.row.col.f32.f16.f16.f32 "
        "{%0,%1,%2,%3}, {%4,%5,%6,%7}, {%8,%9}, {%0,%1,%2,%3};"
        : "+f"(d[0]), "+f"(d[1]), "+f"(d[2]), "+f"(d[3])
        : "r"(a[0]), "r"(a[1]), "r"(a[2]), "r"(a[3]), "r"(b0), "r"(b1));
}

// ---------------------------------------------------------------------------
// Kernel 1: weight -> fp16, reorder K dim to k*256+c
// ---------------------------------------------------------------------------
__global__ void wsplit_kernel(const float* __restrict__ w) {
    int i = blockIdx.x * blockDim.x + threadIdx.x;
    if (i >= OC_ * CK_) return;
    int oc  = i / CK_;
    int rem = i % CK_;
    int c   = rem / K_;
    int k   = rem % K_;
    g_w[(size_t)oc * CK_ + k * C_ + c] = __float2half(w[i]);
}

// ---------------------------------------------------------------------------
// Kernel 2: transpose x (B,C,HW) fp32 -> g_xth (B,HW,C) fp16
// ---------------------------------------------------------------------------
__global__ void __launch_bounds__(256)
transpose_kernel(const float* __restrict__ x) {
    __shared__ float tile[32][33];
    int b  = blockIdx.z;
    int ct = blockIdx.y;
    int pt = blockIdx.x;
    int tx  = threadIdx.x & 31;
    int ty4 = (threadIdx.x >> 5) * 4;

    const float* xb = x + (((size_t)(b * C_ + ct * 32)) << 12) + pt * 32;
#pragma unroll
    for (int i = 0; i < 4; i++)
        tile[ty4 + i][tx] = xb[((size_t)(ty4 + i) << 12) + tx];
    __syncthreads();
    __half* xtb = g_xth + ((size_t)(b * HW_) + pt * 32) * C_ + ct * 32;
#pragma unroll
    for (int i = 0; i < 4; i++)
        xtb[(size_t)(ty4 + i) * C_ + tx] = __float2half(tile[tx][ty4 + i]);
}

// ---------------------------------------------------------------------------
// Kernel 3: im2col (fused sampling prep) — coalesced fp16 gathers along c.
// CTA = (b, 64-pixel tile). Per tap k: each warp computes 8 pixels x 256 c,
// stages fp16 in smem, then writes 256 rows x 64 pix with full 128B/warp
// stores (lane carries a 2-pixel __half2).
// ---------------------------------------------------------------------------
__global__ void __launch_bounds__(256, 4)
im2col_kernel(const float* __restrict__ offset, const float* __restrict__ mask) {
    __shared__ __half stage[64][258];
    int b   = blockIdx.y;
    int p0  = blockIdx.x * 64;
    int tid = threadIdx.x;
    int wid = tid >> 5;
    int lid = tid & 31;

    const __half* xbh = g_xth + ((size_t)b * HW_) * C_;
    size_t colsBase = (size_t)b * CK_ * (size_t)HW_;

    for (int k = 0; k < K_; k++) {
#pragma unroll
        for (int p8 = 0; p8 < 8; p8++) {
            int p    = wid * 8 + p8;
            int pixg = p0 + p;

            float dy = __ldg(&offset[((size_t)(b * 18 + 2 * k) << 12) + pixg]);
            float dx = __ldg(&offset[((size_t)(b * 18 + 2 * k + 1) << 12) + pixg]);
            float m  = __ldg(&mask[((size_t)(b * 9 + k) << 12) + pixg]);
            int ho = pixg >> 6, wo = pixg & 63;
            float py = (float)(k / 3) + (float)(ho - 1) + dy;
            float px = (float)(k % 3) + (float)(wo - 1) + dx;
            float y0f = floorf(py), x0f = floorf(px);
            float wy1 = py - y0f, wx1 = px - x0f;
            float wy0 = 1.0f - wy1, wx0 = 1.0f - wx1;
            int y0 = (int)y0f, x0 = (int)x0f;
            int y1 = y0 + 1, x1 = x0 + 1;
            float v00 = (y0 >= 0 && y0 < H_ && x0 >= 0 && x0 < W_) ? 1.0f : 0.0f;
            float v01 = (y0 >= 0 && y0 < H_ && x1 >= 0 && x1 < W_) ? 1.0f : 0.0f;
            float v10 = (y1 >= 0 && y1 < H_ && x0 >= 0 && x0 < W_) ? 1.0f : 0.0f;
            float v11 = (y1 >= 0 && y1 < H_ && x1 >= 0 && x1 < W_) ? 1.0f : 0.0f;
            int yi0 = min(max(y0, 0), H_ - 1), yi1 = min(max(y1, 0), H_ - 1);
            int xi0 = min(max(x0, 0), W_ - 1), xi1 = min(max(x1, 0), W_ - 1);
            float4 wv = make_float4(wy0 * wx0 * v00 * m, wy0 * wx1 * v01 * m,
                                    wy1 * wx0 * v10 * m, wy1 * wx1 * v11 * m);
            int4 si = make_int4(yi0 * W_ + xi0, yi0 * W_ + xi1,
                                yi1 * W_ + xi0, yi1 * W_ + xi1);

            int co = lid * 4;
            float a0x = 0.f, a0y = 0.f, a0z = 0.f, a0w = 0.f;
            float a1x = 0.f, a1y = 0.f, a1z = 0.f, a1w = 0.f;

            const __half* cp;
            uint2 u;
            __half2 h01, h23;
            float2 f01, f23;
#define CORNER(IDX, WW)                                                        \
            cp = xbh + ((size_t)(IDX) << 8) + co;                              \
            u = *(const uint2*)cp;                                             \
            h01 = *(__half2*)&u.x; h23 = *(__half2*)&u.y;                      \
            f01 = __half22float2(h01); f23 = __half22float2(h23);              \
            a0x += (WW) * f01.x; a0y += (WW) * f01.y;                          \
            a0z += (WW) * f23.x; a0w += (WW) * f23.y;                          \
            u = *(const uint2*)(cp + 128);                                     \
            h01 = *(__half2*)&u.x; h23 = *(__half2*)&u.y;                      \
            f01 = __half22float2(h01); f23 = __half22float2(h23);              \
            a1x += (WW) * f01.x; a1y += (WW) * f01.y;                          \
            a1z += (WW) * f23.x; a1w += (WW) * f23.y;

            CORNER(si.x, wv.x)
            CORNER(si.y, wv.y)
            CORNER(si.z, wv.z)
            CORNER(si.w, wv.w)
#undef CORNER

            *(__half2*)&stage[p][co]       = __floats2half2_rn(a0x, a0y);
            *(__half2*)&stage[p][co + 2]   = __floats2half2_rn(a0z, a0w);
            *(__half2*)&stage[p][co + 128] = __floats2half2_rn(a1x, a1y);
            *(__half2*)&stage[p][co + 130] = __floats2half2_rn(a1z, a1w);
        }
        __syncthreads();

        // write 256 rows x 64 pix: warp wid handles rows c = wid*32 + j,
        // lane carries pixel pair (2*lid, 2*lid+1) -> 128B per warp-store.
        __half* dstBase = g_cols + colsBase + (((size_t)(k * C_)) << 12)
                        + p0 + lid * 2;
#pragma unroll
        for (int j = 0; j < 32; j++) {
            int c = wid * 32 + j;
            __half2 v = __halves2half2(stage[lid * 2][c], stage[lid * 2 + 1][c]);
            *(__half2*)(dstBase + (((size_t)c) << 12)) = v;
        }
        __syncthreads();
    }
}

// ---------------------------------------------------------------------------
// Kernel 4: fp16 HMMA GEMM — 2-stage double buffer (proven structure),
// BK widened 64 -> 96. CTA 128x128, 8 warps (2Mx4N), warp 64x32, m16n8k16.
// ---------------------------------------------------------------------------
#define BKG    96
#define NKIT   (CK_ / BKG)          // 24
#define AROW   104                  // 96 + 8 pad (halves)
#define BROW   136                  // 128 + 8 pad (halves)
#define A_STG  (128 * AROW * 2)     // 26624 B per stage
#define B_STG  (BKG * BROW * 2)     // 26112 B per stage
#define SMEM_BYTES (2 * (A_STG + B_STG))   // 105472 B

__global__ void __launch_bounds__(256, 2)
gemm_mma_kernel(const float* __restrict__ bias, float* __restrict__ out) {
    extern __shared__ __align__(16) __half sm[];

    const int tid   = threadIdx.x;
    const int wid   = tid >> 5;
    const int lid   = tid & 31;
    const int wm    = wid >> 2;
    const int wn    = wid & 3;
    const int nBase = blockIdx.x * 128;
    const int mBase = blockIdx.y * 128;
    const int b     = blockIdx.z;

    const __half* colsB = g_cols + ((size_t)b * CK_ << 12);

    const uint32_t smA = smem_u32(sm);
    const uint32_t smB = smA + 2 * A_STG;

    // ---- hoisted cp.async addresses ----
    // A: 128 rows x 192B -> 1536 chunks -> 6/thread
    uint32_t stA[6];
    const __half* gA[6];
#pragma unroll
    for (int j = 0; j < 6; j++) {
        int piece = tid + j * 256;
        int row = piece / 12, seg = piece % 12;
        stA[j] = smA + (row * AROW + seg * 8) * 2;
        gA[j]  = g_w + (size_t)(mBase + row) * CK_ + seg * 8;
    }
    // B: 96 rows x 256B -> 1536 chunks -> 6/thread
    uint32_t stB[6];
    const __half* gB[6];
#pragma unroll
    for (int j = 0; j < 6; j++) {
        int piece = tid + j * 256;
        int row = piece >> 4, seg = piece & 15;
        stB[j] = smB + (row * BROW + seg * 8) * 2;
        gB[j]  = colsB + ((size_t)row << 12) + nBase + seg * 8;
    }

    // ---- hoisted ldsm read addresses ----
    const uint32_t aRd = smA + ((wm * 64 + (lid & 15)) * AROW
                                + ((lid >> 4) & 1) * 8) * 2;
    const uint32_t bRd = smB + ((lid & 15) * BROW + wn * 32
                                + ((lid >> 4) & 1) * 8) * 2;

    float acc[4][4][4];
#pragma unroll
    for (int i = 0; i < 4; i++)
#pragma unroll
        for (int j = 0; j < 4; j++)
#pragma unroll
            for (int q = 0; q < 4; q++) acc[i][j][q] = 0.0f;

    auto load_stage = [&](int s, int kt) {
        uint32_t oA = (uint32_t)s * A_STG;
        uint32_t oB = (uint32_t)s * B_STG;
#pragma unroll
        for (int j = 0; j < 6; j++)
            cpasync16(stA[j] + oA, gA[j] + kt);
        size_t kb = (size_t)kt << 12;
#pragma unroll
        for (int j = 0; j < 6; j++)
            cpasync16(stB[j] + oB, gB[j] + kb);
        asm volatile("cp.async.commit_group;" ::: "memory");
    };

    load_stage(0, 0);

    for (int i = 0; i < NKIT; i++) {
        int s = i & 1;
        if (i + 1 < NKIT) {
            load_stage(s ^ 1, (i + 1) * BKG);
            asm volatile("cp.async.wait_group 1;" ::: "memory");
        } else {
            asm volatile("cp.async.wait_group 0;" ::: "memory");
        }
        __syncthreads();

        const uint32_t sA = aRd + (uint32_t)s * A_STG;
        const uint32_t sB = bRd + (uint32_t)s * B_STG;
#pragma unroll
        for (int ks = 0; ks < 6; ks++) {
            uint32_t a[4][4];
#pragma unroll
            for (int mt = 0; mt < 4; mt++)
                ldsm_x4(a[mt], sA + mt * (16 * AROW * 2) + ks * 32);
            uint32_t bf[2][4];
#pragma unroll
            for (int pr = 0; pr < 2; pr++)
                ldsm_x4_t(bf[pr], sB + ks * (16 * BROW * 2) + pr * 32);
#pragma unroll
            for (int mt = 0; mt < 4; mt++)
#pragma unroll
                for (int nt = 0; nt < 4; nt++)
                    mma_f16(acc[mt][nt], a[mt],
                            bf[nt >> 1][(nt & 1) * 2], bf[nt >> 1][(nt & 1) * 2 + 1]);
        }
        __syncthreads();
    }

    // Epilogue
    const int r  = lid >> 2;
    const int cc = (lid & 3) * 2;
#pragma unroll
    for (int mt = 0; mt < 4; mt++) {
        int oc0 = mBase + wm * 64 + mt * 16 + r;
        float bz0 = bias[oc0];
        float bz1 = bias[oc0 + 8];
        float* o0 = out + (((size_t)(b * OC_ + oc0)) << 12) + nBase;
        float* o1 = out + (((size_t)(b * OC_ + oc0 + 8)) << 12) + nBase;
#pragma unroll
        for (int nt = 0; nt < 4; nt++) {
            int px = wn * 32 + nt * 8 + cc;
            float2 v0 = make_float2(acc[mt][nt][0] + bz0, acc[mt][nt][1] + bz0);
            float2 v1 = make_float2(acc[mt][nt][2] + bz1, acc[mt][nt][3] + bz1);
            *(float2*)(o0 + px) = v0;
            *(float2*)(o1 + px) = v1;
        }
    }
}

// ---------------------------------------------------------------------------
extern "C" void kernel_launch(void* const* d_in, const int* in_sizes, int n_in,
                              void* d_out, int out_size) {
    const float* x      = (const float*)d_in[0];
    const float* offset = (const float*)d_in[1];
    const float* mask   = (const float*)d_in[2];
    const float* weight = (const float*)d_in[3];
    const float* bias   = (const float*)d_in[4];
    float* out          = (float*)d_out;

    wsplit_kernel<<<(OC_ * CK_ + 255) / 256, 256>>>(weight);
    {
        dim3 grid(128, 8, 8);
        transpose_kernel<<<grid, 256>>>(x);
    }
    {
        dim3 grid(HW_ / 64, B_);
        im2col_kernel<<<grid, 256>>>(offset, mask);
    }
    {
        static bool attrSet = false;
        if (!attrSet) {
            cudaFuncSetAttribute(gemm_mma_kernel,
                                 cudaFuncAttributeMaxDynamicSharedMemorySize,
                                 SMEM_BYTES);
            attrSet = true;
        }
        dim3 grid(HW_ / 128, OC_ / 128, B_);
        gemm_mma_kernel<<<grid, 256, SMEM_BYTES>>>(bias, out);
    }
}

// round 13
// speedup vs baseline: 1.5581x; 1.5581x over previous
#include <cuda_runtime.h>
#include <cuda_fp16.h>
#include <cstdint>

// Problem constants
#define B_   8
#define C_   256
#define H_   64
#define W_   64
#define OC_  256
#define K_   9
#define HW_  4096
#define CK_  2304

// ---------------------------------------------------------------------------
// Device scratch (allocation-free rule)
// ---------------------------------------------------------------------------
__device__ __align__(256) __half g_cols[(size_t)B_ * CK_ * HW_];  // 151 MB, [b][k*256+c][pix]
__device__ __align__(256) __half g_w[OC_ * CK_];                  // [oc][k*256+c]
__device__ __align__(256) __half g_xth[(size_t)B_ * HW_ * C_];    // 67 MB, [b][pix][c] fp16

// ---------------------------------------------------------------------------
// Helpers
// ---------------------------------------------------------------------------
__device__ __forceinline__ uint32_t smem_u32(const void* p) {
    uint32_t a;
    asm("{ .reg .u64 t; cvta.to.shared.u64 t, %1; cvt.u32.u64 %0, t; }"
        : "=r"(a) : "l"(p));
    return a;
}

__device__ __forceinline__ void cpasync16(uint32_t s, const void* g) {
    asm volatile("cp.async.cg.shared.global [%0], [%1], 16;" :: "r"(s), "l"(g));
}

__device__ __forceinline__ void ldsm_x4(uint32_t* r, uint32_t addr) {
    asm volatile("ldmatrix.sync.aligned.m8n8.x4.shared.b16 {%0,%1,%2,%3}, [%4];"
                 : "=r"(r[0]), "=r"(r[1]), "=r"(r[2]), "=r"(r[3]) : "r"(addr));
}

__device__ __forceinline__ void ldsm_x4_t(uint32_t* r, uint32_t addr) {
    asm volatile("ldmatrix.sync.aligned.m8n8.x4.trans.shared.b16 {%0,%1,%2,%3}, [%4];"
                 : "=r"(r[0]), "=r"(r[1]), "=r"(r[2]), "=r"(r[3]) : "r"(addr));
}

__device__ __forceinline__ void mma_f16(float* d, const uint32_t* a,
                                        uint32_t b0, uint32_t b1) {
    asm volatile(
        "mma.sync.aligned.m16n8k16.row.col.f32.f16.f16.f32 "
        "{%0,%1,%2,%3}, {%4,%5,%6,%7}, {%8,%9}, {%0,%1,%2,%3};"
        : "+f"(d[0]), "+f"(d[1]), "+f"(d[2]), "+f"(d[3])
        : "r"(a[0]), "r"(a[1]), "r"(a[2]), "r"(a[3]), "r"(b0), "r"(b1));
}

// ---------------------------------------------------------------------------
// Kernel 1: weight -> fp16, reorder K dim to k*256+c
// ---------------------------------------------------------------------------
__global__ void wsplit_kernel(const float* __restrict__ w) {
    int i = blockIdx.x * blockDim.x + threadIdx.x;
    if (i >= OC_ * CK_) return;
    int oc  = i / CK_;
    int rem = i % CK_;
    int c   = rem / K_;
    int k   = rem % K_;
    g_w[(size_t)oc * CK_ + k * C_ + c] = __float2half(w[i]);
}

// ---------------------------------------------------------------------------
// Kernel 2: transpose x (B,C,HW) fp32 -> g_xth (B,HW,C) fp16
// ---------------------------------------------------------------------------
__global__ void __launch_bounds__(256)
transpose_kernel(const float* __restrict__ x) {
    __shared__ float tile[32][33];
    int b  = blockIdx.z;
    int ct = blockIdx.y;
    int pt = blockIdx.x;
    int tx  = threadIdx.x & 31;
    int ty4 = (threadIdx.x >> 5) * 4;

    const float* xb = x + (((size_t)(b * C_ + ct * 32)) << 12) + pt * 32;
#pragma unroll
    for (int i = 0; i < 4; i++)
        tile[ty4 + i][tx] = xb[((size_t)(ty4 + i) << 12) + tx];
    __syncthreads();
    __half* xtb = g_xth + ((size_t)(b * HW_) + pt * 32) * C_ + ct * 32;
#pragma unroll
    for (int i = 0; i < 4; i++)
        xtb[(size_t)(ty4 + i) * C_ + tx] = __float2half(tile[tx][ty4 + i]);
}

// ---------------------------------------------------------------------------
// Kernel 3: im2col (fused sampling prep) — R11 proven version (32-pix tiles).
// ---------------------------------------------------------------------------
__global__ void __launch_bounds__(256, 4)
im2col_kernel(const float* __restrict__ offset, const float* __restrict__ mask) {
    __shared__ __half stage[32][258];
    int b   = blockIdx.y;
    int p0  = blockIdx.x * 32;
    int tid = threadIdx.x;
    int wid = tid >> 5;
    int lid = tid & 31;

    const __half* xbh = g_xth + ((size_t)b * HW_) * C_;
    size_t colsBase = (size_t)b * CK_ * (size_t)HW_;

    for (int k = 0; k < K_; k++) {
#pragma unroll
        for (int p4 = 0; p4 < 4; p4++) {
            int p    = wid * 4 + p4;
            int pixg = p0 + p;

            float dy = __ldg(&offset[((size_t)(b * 18 + 2 * k) << 12) + pixg]);
            float dx = __ldg(&offset[((size_t)(b * 18 + 2 * k + 1) << 12) + pixg]);
            float m  = __ldg(&mask[((size_t)(b * 9 + k) << 12) + pixg]);
            int ho = pixg >> 6, wo = pixg & 63;
            float py = (float)(k / 3) + (float)(ho - 1) + dy;
            float px = (float)(k % 3) + (float)(wo - 1) + dx;
            float y0f = floorf(py), x0f = floorf(px);
            float wy1 = py - y0f, wx1 = px - x0f;
            float wy0 = 1.0f - wy1, wx0 = 1.0f - wx1;
            int y0 = (int)y0f, x0 = (int)x0f;
            int y1 = y0 + 1, x1 = x0 + 1;
            float v00 = (y0 >= 0 && y0 < H_ && x0 >= 0 && x0 < W_) ? 1.0f : 0.0f;
            float v01 = (y0 >= 0 && y0 < H_ && x1 >= 0 && x1 < W_) ? 1.0f : 0.0f;
            float v10 = (y1 >= 0 && y1 < H_ && x0 >= 0 && x0 < W_) ? 1.0f : 0.0f;
            float v11 = (y1 >= 0 && y1 < H_ && x1 >= 0 && x1 < W_) ? 1.0f : 0.0f;
            int yi0 = min(max(y0, 0), H_ - 1), yi1 = min(max(y1, 0), H_ - 1);
            int xi0 = min(max(x0, 0), W_ - 1), xi1 = min(max(x1, 0), W_ - 1);
            float4 wv = make_float4(wy0 * wx0 * v00 * m, wy0 * wx1 * v01 * m,
                                    wy1 * wx0 * v10 * m, wy1 * wx1 * v11 * m);
            int4 si = make_int4(yi0 * W_ + xi0, yi0 * W_ + xi1,
                                yi1 * W_ + xi0, yi1 * W_ + xi1);

            int co = lid * 4;
            float a0x = 0.f, a0y = 0.f, a0z = 0.f, a0w = 0.f;
            float a1x = 0.f, a1y = 0.f, a1z = 0.f, a1w = 0.f;

            const __half* cp;
            uint2 u;
            __half2 h01, h23;
            float2 f01, f23;
#define CORNER(IDX, WW)                                                        \
            cp = xbh + ((size_t)(IDX) << 8) + co;                              \
            u = *(const uint2*)cp;                                             \
            h01 = *(__half2*)&u.x; h23 = *(__half2*)&u.y;                      \
            f01 = __half22float2(h01); f23 = __half22float2(h23);              \
            a0x += (WW) * f01.x; a0y += (WW) * f01.y;                          \
            a0z += (WW) * f23.x; a0w += (WW) * f23.y;                          \
            u = *(const uint2*)(cp + 128);                                     \
            h01 = *(__half2*)&u.x; h23 = *(__half2*)&u.y;                      \
            f01 = __half22float2(h01); f23 = __half22float2(h23);              \
            a1x += (WW) * f01.x; a1y += (WW) * f01.y;                          \
            a1z += (WW) * f23.x; a1w += (WW) * f23.y;

            CORNER(si.x, wv.x)
            CORNER(si.y, wv.y)
            CORNER(si.z, wv.z)
            CORNER(si.w, wv.w)
#undef CORNER

            *(__half2*)&stage[p][co]       = __floats2half2_rn(a0x, a0y);
            *(__half2*)&stage[p][co + 2]   = __floats2half2_rn(a0z, a0w);
            *(__half2*)&stage[p][co + 128] = __floats2half2_rn(a1x, a1y);
            *(__half2*)&stage[p][co + 130] = __floats2half2_rn(a1z, a1w);
        }
        __syncthreads();

        __half* dst = g_cols + colsBase + (((size_t)(k * C_)) << 12) + p0 + lid;
#pragma unroll
        for (int j = 0; j < 32; j++) {
            int c = wid * 32 + j;
            dst[((size_t)c) << 12] = stage[lid][c];
        }
        __syncthreads();
    }
}

// ---------------------------------------------------------------------------
// Kernel 4: fp16 HMMA GEMM — BK=64 (proven optimum), 3-stage cp.async
// pipeline with COMPILE-TIME stage constants (manual 3x body unroll) and
// ONE __syncthreads per K-iteration. CTA 128x128, 8 warps (2Mx4N).
// ---------------------------------------------------------------------------
#define BKG    64
#define NKIT   (CK_ / BKG)          // 36 (= 12 * 3)
#define AROW   72                   // 64 + 8 pad (halves)
#define BROW   136                  // 128 + 8 pad (halves)
#define A_STG  (128 * AROW * 2)     // 18432 B per stage
#define B_STG  (BKG * BROW * 2)     // 17408 B per stage
#define SMEM_BYTES (3 * (A_STG + B_STG))   // 107520 B

__device__ __forceinline__ void compute_chunk(uint32_t sA, uint32_t sB,
                                              float acc[4][4][4]) {
#pragma unroll
    for (int ks = 0; ks < 4; ks++) {
        uint32_t a[4][4];
#pragma unroll
        for (int mt = 0; mt < 4; mt++)
            ldsm_x4(a[mt], sA + mt * (16 * AROW * 2) + ks * 32);
        uint32_t bf[2][4];
#pragma unroll
        for (int pr = 0; pr < 2; pr++)
            ldsm_x4_t(bf[pr], sB + ks * (16 * BROW * 2) + pr * 32);
#pragma unroll
        for (int mt = 0; mt < 4; mt++)
#pragma unroll
            for (int nt = 0; nt < 4; nt++)
                mma_f16(acc[mt][nt], a[mt],
                        bf[nt >> 1][(nt & 1) * 2], bf[nt >> 1][(nt & 1) * 2 + 1]);
    }
}

__global__ void __launch_bounds__(256, 2)
gemm_mma_kernel(const float* __restrict__ bias, float* __restrict__ out) {
    extern __shared__ __align__(16) __half sm[];

    const int tid   = threadIdx.x;
    const int wid   = tid >> 5;
    const int lid   = tid & 31;
    const int wm    = wid >> 2;
    const int wn    = wid & 3;
    const int nBase = blockIdx.x * 128;
    const int mBase = blockIdx.y * 128;
    const int b     = blockIdx.z;

    const __half* colsB = g_cols + ((size_t)b * CK_ << 12);

    const uint32_t smA = smem_u32(sm);
    const uint32_t smB = smA + 3 * A_STG;

    // ---- hoisted cp.async addresses (A: 4 chunks/thread, B: 4 chunks/thread)
    uint32_t stA[4];
    const __half* gA[4];
#pragma unroll
    for (int j = 0; j < 4; j++) {
        int piece = tid + j * 256;
        int row = piece >> 3, seg = piece & 7;
        stA[j] = smA + (row * AROW + seg * 8) * 2;
        gA[j]  = g_w + (size_t)(mBase + row) * CK_ + seg * 8;
    }
    uint32_t stB[4];
    const __half* gB[4];
#pragma unroll
    for (int j = 0; j < 4; j++) {
        int piece = tid + j * 256;
        int row = piece >> 4, seg = piece & 15;
        stB[j] = smB + (row * BROW + seg * 8) * 2;
        gB[j]  = colsB + ((size_t)row << 12) + nBase + seg * 8;
    }

    // ---- hoisted ldsm read addresses ----
    const uint32_t aRd = smA + ((wm * 64 + (lid & 15)) * AROW
                                + ((lid >> 4) & 1) * 8) * 2;
    const uint32_t bRd = smB + ((lid & 15) * BROW + wn * 32
                                + ((lid >> 4) & 1) * 8) * 2;

    float acc[4][4][4];
#pragma unroll
    for (int i = 0; i < 4; i++)
#pragma unroll
        for (int j = 0; j < 4; j++)
#pragma unroll
            for (int q = 0; q < 4; q++) acc[i][j][q] = 0.0f;

    auto load_stage = [&](uint32_t oA, uint32_t oB, int kt) {
#pragma unroll
        for (int j = 0; j < 4; j++)
            cpasync16(stA[j] + oA, gA[j] + kt);
        size_t kb = (size_t)kt << 12;
#pragma unroll
        for (int j = 0; j < 4; j++)
            cpasync16(stB[j] + oB, gB[j] + kb);
        asm volatile("cp.async.commit_group;" ::: "memory");
    };

    load_stage(0, 0, 0);
    load_stage(A_STG, B_STG, BKG);

    // One body per stage, S is a literal -> all smem offsets compile-time.
#define GBODY(S, IDX)                                                          \
    {                                                                          \
        if ((IDX) == NKIT - 1)                                                 \
            asm volatile("cp.async.wait_group 0;" ::: "memory");               \
        else                                                                   \
            asm volatile("cp.async.wait_group 1;" ::: "memory");               \
        __syncthreads();                                                       \
        int nk = (IDX) + 2;                                                    \
        if (nk < NKIT)                                                         \
            load_stage((((S) + 2) % 3) * A_STG, (((S) + 2) % 3) * B_STG,       \
                       nk * BKG);                                              \
        compute_chunk(aRd + (S) * A_STG, bRd + (S) * B_STG, acc);              \
    }

    for (int i = 0; i < NKIT; i += 3) {
        GBODY(0, i)
        GBODY(1, i + 1)
        GBODY(2, i + 2)
    }
#undef GBODY

    // Epilogue
    const int r  = lid >> 2;
    const int cc = (lid & 3) * 2;
#pragma unroll
    for (int mt = 0; mt < 4; mt++) {
        int oc0 = mBase + wm * 64 + mt * 16 + r;
        float bz0 = bias[oc0];
        float bz1 = bias[oc0 + 8];
        float* o0 = out + (((size_t)(b * OC_ + oc0)) << 12) + nBase;
        float* o1 = out + (((size_t)(b * OC_ + oc0 + 8)) << 12) + nBase;
#pragma unroll
        for (int nt = 0; nt < 4; nt++) {
            int px = wn * 32 + nt * 8 + cc;
            float2 v0 = make_float2(acc[mt][nt][0] + bz0, acc[mt][nt][1] + bz0);
            float2 v1 = make_float2(acc[mt][nt][2] + bz1, acc[mt][nt][3] + bz1);
            *(float2*)(o0 + px) = v0;
            *(float2*)(o1 + px) = v1;
        }
    }
}

// ---------------------------------------------------------------------------
extern "C" void kernel_launch(void* const* d_in, const int* in_sizes, int n_in,
                              void* d_out, int out_size) {
    const float* x      = (const float*)d_in[0];
    const float* offset = (const float*)d_in[1];
    const float* mask   = (const float*)d_in[2];
    const float* weight = (const float*)d_in[3];
    const float* bias   = (const float*)d_in[4];
    float* out          = (float*)d_out;

    wsplit_kernel<<<(OC_ * CK_ + 255) / 256, 256>>>(weight);
    {
        dim3 grid(128, 8, 8);
        transpose_kernel<<<grid, 256>>>(x);
    }
    {
        dim3 grid(HW_ / 32, B_);
        im2col_kernel<<<grid, 256>>>(offset, mask);
    }
    {
        static bool attrSet = false;
        if (!attrSet) {
            cudaFuncSetAttribute(gemm_mma_kernel,
                                 cudaFuncAttributeMaxDynamicSharedMemorySize,
                                 SMEM_BYTES);
            attrSet = true;
        }
        dim3 grid(HW_ / 128, OC_ / 128, B_);
        gemm_mma_kernel<<<grid, 256, SMEM_BYTES>>>(bias, out);
    }
}